// round 14
// baseline (speedup 1.0000x reference)
#include <cuda_runtime.h>
#include <cuda_fp16.h>

#define Bc 2
#define Hc 12
#define Sc 2048
#define Dc 64
#define TQ 128
#define TK 64
#define NTH 128
#define STRD 72           // smem row stride in halves (64 + 8 pad, 144B)
#define SCALE 0.125f      // 1/sqrt(64)
#define NKT (Sc / TK)     // 32

// g_fmp (uint4): (((b*16+qt)*32+kt)*8 + w*2+mb)*128 + part*32 + lane
__device__ __align__(16) uint4 g_fmp[(size_t)Bc * 16 * 32 * 8 * 128];
__device__ __align__(16) __half g_kh[(size_t)Bc * Hc * Sc * Dc];
__device__ __align__(16) __half g_vh[(size_t)Bc * Hc * Sc * Dc];

__global__ void prep_fm_kernel(const float* __restrict__ freq,
                               const int*  __restrict__ mask) {
    unsigned idx = blockIdx.x * blockDim.x + threadIdx.x;   // one uint4 out
    int lane = idx & 31, part = (idx >> 5) & 3, mbw = (idx >> 7) & 7;
    int kt = (idx >> 10) & 31, qt = (idx >> 15) & 15, b = idx >> 19;
    int w = mbw >> 1, mb = mbw & 1;
    int g = lane >> 2, tg = lane & 3;
    int q = qt * TQ + w * 32 + mb * 16 + g + ((part >> 1) << 3);
    const float* fr = freq + ((size_t)b * Sc + q) * Sc;
    const int*   mr = mask + ((size_t)b * Sc + q) * Sc;
    int kbase = kt * 64 + (part & 1) * 32 + tg * 2;
    unsigned out[4];
    #pragma unroll
    for (int j = 0; j < 4; ++j) {
        int k = kbase + j * 8;
        float2 f = *(const float2*)(fr + k);
        int2   m = *(const int2*)(mr + k);
        __half2 h = __floats2half2_rn(m.x ? __logf(f.x) : -60000.0f,
                                      m.y ? __logf(f.y) : -60000.0f);
        out[j] = *(unsigned*)&h;
    }
    g_fmp[idx] = make_uint4(out[0], out[1], out[2], out[3]);
}

__global__ void prep_kv_kernel(const float* __restrict__ K,
                               const float* __restrict__ V) {
    size_t base = ((size_t)blockIdx.x * blockDim.x + threadIdx.x) * 8;
    float4 a = *(const float4*)(K + base);
    float4 b = *(const float4*)(K + base + 4);
    __half2 h0 = __floats2half2_rn(a.x, a.y), h1 = __floats2half2_rn(a.z, a.w);
    __half2 h2 = __floats2half2_rn(b.x, b.y), h3 = __floats2half2_rn(b.z, b.w);
    uint4 u;
    u.x = *(unsigned*)&h0; u.y = *(unsigned*)&h1;
    u.z = *(unsigned*)&h2; u.w = *(unsigned*)&h3;
    *(uint4*)(g_kh + base) = u;
    a = *(const float4*)(V + base);
    b = *(const float4*)(V + base + 4);
    h0 = __floats2half2_rn(a.x, a.y); h1 = __floats2half2_rn(a.z, a.w);
    h2 = __floats2half2_rn(b.x, b.y); h3 = __floats2half2_rn(b.z, b.w);
    u.x = *(unsigned*)&h0; u.y = *(unsigned*)&h1;
    u.z = *(unsigned*)&h2; u.w = *(unsigned*)&h3;
    *(uint4*)(g_vh + base) = u;
}

__device__ __forceinline__ void mma_f16(float* c, const unsigned* a, const unsigned* b) {
    asm volatile(
        "mma.sync.aligned.m16n8k16.row.col.f32.f16.f16.f32 "
        "{%0,%1,%2,%3}, {%4,%5,%6,%7}, {%8,%9}, {%0,%1,%2,%3};\n"
        : "+f"(c[0]), "+f"(c[1]), "+f"(c[2]), "+f"(c[3])
        : "r"(a[0]), "r"(a[1]), "r"(a[2]), "r"(a[3]), "r"(b[0]), "r"(b[1]));
}

__device__ __forceinline__ void ldsm4(unsigned& r0, unsigned& r1, unsigned& r2,
                                      unsigned& r3, unsigned addr) {
    asm volatile("ldmatrix.sync.aligned.m8n8.x4.shared.b16 {%0,%1,%2,%3}, [%4];"
                 : "=r"(r0), "=r"(r1), "=r"(r2), "=r"(r3) : "r"(addr));
}

__device__ __forceinline__ void ldsm4t(unsigned& r0, unsigned& r1, unsigned& r2,
                                       unsigned& r3, unsigned addr) {
    asm volatile("ldmatrix.sync.aligned.m8n8.x4.trans.shared.b16 {%0,%1,%2,%3}, [%4];"
                 : "=r"(r0), "=r"(r1), "=r"(r2), "=r"(r3) : "r"(addr));
}

__global__ void __launch_bounds__(NTH)
attn_kernel(const float* __restrict__ Q, float* __restrict__ Out,
            float* __restrict__ Pout, int writep) {
    // Ks | Vs (64 x STRD each); Q prologue overlays both (128 x STRD)
    __shared__ __align__(16) __half smem_buf[2 * TK * STRD];
    __half* Ks = smem_buf;
    __half* Vs = smem_buf + TK * STRD;

    const int tid = threadIdx.x;
    const int w = tid >> 5, lane = tid & 31;
    const int g = lane >> 2, tg = lane & 3;
    const int wq = w * 32;
    const int h = blockIdx.x, qt = blockIdx.y, b = blockIdx.z;
    const int q0 = qt * TQ;

    const size_t bh = (size_t)b * Hc + h;
    const float*  Qg = Q + (bh * Sc + q0) * Dc;
    const __half* Kh = g_kh + bh * Sc * Dc;
    const __half* Vh = g_vh + bh * Sc * Dc;
    float* Og = Out + (bh * Sc + q0) * Dc;
    float* Pg = Pout + (bh * Sc + q0) * Sc;

    // FM fragments (h-independent -> 12-head L2 reuse)
    const uint4* fmb = g_fmp +
                 ((((size_t)b * 16 + qt) * NKT) * 8 + w * 2) * 128 + lane;

    const unsigned smem_u = (unsigned)__cvta_generic_to_shared(smem_buf);
    const unsigned vs_u   = smem_u + TK * STRD * 2;
    // B (K): m0=(n0-7,klo) m1=(n0-7,khi) m2=(n8-15,klo) m3=(n8-15,khi)
    const int brow = ((lane >> 4) & 1) * 8 + (lane & 7);
    const int bcol = ((lane >> 3) & 1) * 8;
    const unsigned addrB = smem_u + ((brow * STRD + bcol) << 1);
    // V (trans)
    const int vrow = ((lane >> 3) & 1) * 8 + (lane & 7);
    const int vcol = ((lane >> 4) & 1) * 8;
    const unsigned addrV = vs_u + ((vrow * STRD + vcol) << 1);

    // ---- Q prologue: stage fp32->fp16 (all 128 rows), load A-fragments ----
    #pragma unroll
    for (int i = tid; i < TQ * 16; i += NTH) {
        int r = i >> 4, c = (i & 15) * 4;
        float4 v = *(const float4*)(Qg + (size_t)r * Dc + c);
        __half2 p0 = __floats2half2_rn(v.x, v.y), p1 = __floats2half2_rn(v.z, v.w);
        uint2 u; u.x = *(unsigned*)&p0; u.y = *(unsigned*)&p1;
        *(uint2*)(smem_buf + r * STRD + c) = u;
    }
    __syncthreads();
    unsigned qa[2][4][4];
    #pragma unroll
    for (int mb = 0; mb < 2; ++mb) {
        unsigned addrA = smem_u +
            (((wq + 16 * mb + (lane & 15)) * STRD + (lane >> 4) * 8) << 1);
        #pragma unroll
        for (int ks = 0; ks < 4; ++ks)
            ldsm4(qa[mb][ks][0], qa[mb][ks][1], qa[mb][ks][2], qa[mb][ks][3],
                  addrA + ks * 32);
    }

    // ---------------- pass 1: Z only (no scratch) ----------------
    float z[2][2] = {{0.0f, 0.0f}, {0.0f, 0.0f}};
    for (int kt = 0; kt < NKT; ++kt) {
        uint4 fm[2][4];
        #pragma unroll
        for (int mb = 0; mb < 2; ++mb) {
            const uint4* fp = fmb + ((size_t)kt * 8 + mb) * 128;
            fm[mb][0] = fp[0];  fm[mb][1] = fp[32];
            fm[mb][2] = fp[64]; fm[mb][3] = fp[96];
        }

        __syncthreads();
        #pragma unroll
        for (int i = tid; i < TK * 8; i += NTH) {      // K tile (uint4 copy)
            int r = i >> 3, c = (i & 7) * 8;
            *(uint4*)(Ks + r * STRD + c) =
                *(const uint4*)(Kh + (size_t)(kt * TK + r) * Dc + c);
        }
        __syncthreads();

        float sacc[2][8][4];
        #pragma unroll
        for (int mb = 0; mb < 2; ++mb)
            #pragma unroll
            for (int nt = 0; nt < 8; ++nt)
                sacc[mb][nt][0] = sacc[mb][nt][1] = sacc[mb][nt][2] = sacc[mb][nt][3] = 0.0f;

        #pragma unroll
        for (int ks = 0; ks < 4; ++ks) {
            unsigned bf[4][4];
            #pragma unroll
            for (int ntp = 0; ntp < 4; ++ntp)
                ldsm4(bf[ntp][0], bf[ntp][1], bf[ntp][2], bf[ntp][3],
                      addrB + (ntp * 16 * STRD + ks * 16) * 2);
            #pragma unroll
            for (int mb = 0; mb < 2; ++mb)
                #pragma unroll
                for (int ntp = 0; ntp < 4; ++ntp) {
                    mma_f16(sacc[mb][2 * ntp],     qa[mb][ks], &bf[ntp][0]);
                    mma_f16(sacc[mb][2 * ntp + 1], qa[mb][ks], &bf[ntp][2]);
                }
        }

        #pragma unroll
        for (int mb = 0; mb < 2; ++mb) {
            #pragma unroll
            for (int nt = 0; nt < 8; ++nt) {
                unsigned flo_u = ((const unsigned*)&fm[mb][nt >> 2])[nt & 3];
                unsigned fhi_u = ((const unsigned*)&fm[mb][2 + (nt >> 2)])[nt & 3];
                float2 flo = __half22float2(*(__half2*)&flo_u);
                float2 fhi = __half22float2(*(__half2*)&fhi_u);
                z[mb][0] += __expf(fmaf(sacc[mb][nt][0], SCALE, flo.x))
                          + __expf(fmaf(sacc[mb][nt][1], SCALE, flo.y));
                z[mb][1] += __expf(fmaf(sacc[mb][nt][2], SCALE, fhi.x))
                          + __expf(fmaf(sacc[mb][nt][3], SCALE, fhi.y));
            }
        }
    }
    float iz[2][2];
    #pragma unroll
    for (int mb = 0; mb < 2; ++mb)
        #pragma unroll
        for (int hf = 0; hf < 2; ++hf) {
            float zz = z[mb][hf];
            zz += __shfl_xor_sync(0xffffffffu, zz, 1);
            zz += __shfl_xor_sync(0xffffffffu, zz, 2);
            iz[mb][hf] = 1.0f / zz;
        }

    // -------- pass 2: recompute scores per-mb, emit P, accumulate O --------
    float oacc[2][8][4];
    #pragma unroll
    for (int mb = 0; mb < 2; ++mb)
        #pragma unroll
        for (int nt = 0; nt < 8; ++nt)
            oacc[mb][nt][0] = oacc[mb][nt][1] = oacc[mb][nt][2] = oacc[mb][nt][3] = 0.0f;

    float2* Pp[2][2];
    #pragma unroll
    for (int mb = 0; mb < 2; ++mb) {
        Pp[mb][0] = (float2*)(Pg + (size_t)(wq + 16 * mb + g) * Sc) + tg;
        Pp[mb][1] = (float2*)(Pg + (size_t)(wq + 16 * mb + g + 8) * Sc) + tg;
    }

    for (int kt = 0; kt < NKT; ++kt) {
        __syncthreads();
        #pragma unroll
        for (int i = tid; i < TK * 8; i += NTH) {      // K tile
            int r = i >> 3, c = (i & 7) * 8;
            *(uint4*)(Ks + r * STRD + c) =
                *(const uint4*)(Kh + (size_t)(kt * TK + r) * Dc + c);
        }
        #pragma unroll
        for (int i = tid; i < TK * 8; i += NTH) {      // V tile
            int r = i >> 3, c = (i & 7) * 8;
            *(uint4*)(Vs + r * STRD + c) =
                *(const uint4*)(Vh + (size_t)(kt * TK + r) * Dc + c);
        }
        __syncthreads();

        // one m-block at a time: halves live sacc (register control)
        #pragma unroll
        for (int mb = 0; mb < 2; ++mb) {
            float sacc[8][4];
            #pragma unroll
            for (int nt = 0; nt < 8; ++nt)
                sacc[nt][0] = sacc[nt][1] = sacc[nt][2] = sacc[nt][3] = 0.0f;

            #pragma unroll
            for (int ks = 0; ks < 4; ++ks) {
                #pragma unroll
                for (int ntp = 0; ntp < 4; ++ntp) {
                    unsigned b0, b1, b2, b3;
                    ldsm4(b0, b1, b2, b3,
                          addrB + (ntp * 16 * STRD + ks * 16) * 2);
                    unsigned blo[2] = {b0, b1}, bhi[2] = {b2, b3};
                    mma_f16(sacc[2 * ntp],     qa[mb][ks], blo);
                    mma_f16(sacc[2 * ntp + 1], qa[mb][ks], bhi);
                }
            }

            const uint4* fp = fmb + ((size_t)kt * 8 + mb) * 128;
            uint4 fm0 = fp[0], fm1 = fp[32], fm2 = fp[64], fm3 = fp[96];

            unsigned sl[8], sh[8];
            #pragma unroll
            for (int nt = 0; nt < 8; ++nt) {
                unsigned flo_u = (nt < 4) ? ((const unsigned*)&fm0)[nt & 3]
                                          : ((const unsigned*)&fm1)[nt & 3];
                unsigned fhi_u = (nt < 4) ? ((const unsigned*)&fm2)[nt & 3]
                                          : ((const unsigned*)&fm3)[nt & 3];
                float2 flo = __half22float2(*(__half2*)&flo_u);
                float2 fhi = __half22float2(*(__half2*)&fhi_u);
                float p0 = __expf(fmaf(sacc[nt][0], SCALE, flo.x));
                float p1 = __expf(fmaf(sacc[nt][1], SCALE, flo.y));
                float p2 = __expf(fmaf(sacc[nt][2], SCALE, fhi.x));
                float p3 = __expf(fmaf(sacc[nt][3], SCALE, fhi.y));
                if (writep) {
                    __stwt(Pp[mb][0] + kt * 32 + nt * 4,
                           make_float2(p0 * iz[mb][0], p1 * iz[mb][0]));
                    __stwt(Pp[mb][1] + kt * 32 + nt * 4,
                           make_float2(p2 * iz[mb][1], p3 * iz[mb][1]));
                }
                __half2 hlo = __floats2half2_rn(p0, p1);
                __half2 hhi = __floats2half2_rn(p2, p3);
                sl[nt] = *(unsigned*)&hlo;
                sh[nt] = *(unsigned*)&hhi;
            }

            #pragma unroll
            for (int ks2 = 0; ks2 < 4; ++ks2) {
                unsigned a[4] = {sl[2 * ks2], sh[2 * ks2],
                                 sl[2 * ks2 + 1], sh[2 * ks2 + 1]};
                #pragma unroll
                for (int ntp = 0; ntp < 4; ++ntp) {
                    unsigned v0, v1, v2, v3;
                    ldsm4t(v0, v1, v2, v3,
                           addrV + (ks2 * 16 * STRD + ntp * 16) * 2);
                    unsigned blo[2] = {v0, v1}, bhi[2] = {v2, v3};
                    mma_f16(oacc[mb][2 * ntp],     a, blo);
                    mma_f16(oacc[mb][2 * ntp + 1], a, bhi);
                }
            }
        }
    }

    // scale by 1/Z and write O tile
    #pragma unroll
    for (int mb = 0; mb < 2; ++mb) {
        float* o0 = Og + (size_t)(wq + 16 * mb + g) * Dc;
        float* o1 = Og + (size_t)(wq + 16 * mb + g + 8) * Dc;
        #pragma unroll
        for (int nt = 0; nt < 8; ++nt) {
            int col = nt * 8 + 2 * tg;
            *(float2*)(o0 + col) = make_float2(oacc[mb][nt][0] * iz[mb][0],
                                               oacc[mb][nt][1] * iz[mb][0]);
            *(float2*)(o1 + col) = make_float2(oacc[mb][nt][2] * iz[mb][1],
                                               oacc[mb][nt][3] * iz[mb][1]);
        }
    }
}

extern "C" void kernel_launch(void* const* d_in, const int* in_sizes, int n_in,
                              void* d_out, int out_size) {
    const float* Q    = (const float*)d_in[0];
    const float* K    = (const float*)d_in[1];
    const float* V    = (const float*)d_in[2];
    const float* freq = (const float*)d_in[3];
    const int*   mask = (const int*)d_in[4];

    const size_t out_elems = (size_t)Bc * Hc * Sc * Dc;   // 3,145,728
    float* Out  = (float*)d_out;
    float* Pout = (float*)d_out + out_elems;              // p_attn follows out
    int writep  = (out_size > (int)out_elems) ? 1 : 0;

    {
        int total = Bc * 16 * 32 * 8 * 128;               // one thread per uint4
        prep_fm_kernel<<<total / 256, 256>>>(freq, mask);
    }
    {
        int total = Bc * Hc * Sc * Dc;
        prep_kv_kernel<<<total / (256 * 8), 256>>>(K, V);
    }
    {
        dim3 grid(Hc, Sc / TQ, Bc);
        attn_kernel<<<grid, NTH>>>(Q, Out, Pout, writep);
    }
}

// round 15
// speedup vs baseline: 1.1137x; 1.1137x over previous
#include <cuda_runtime.h>
#include <cuda_fp16.h>

#define Bc 2
#define Hc 12
#define Sc 2048
#define Dc 64
#define TQ 128
#define TK 64
#define NTH 256           // 8 warps x 16 rows
#define STRD 72           // smem row stride in halves (64 + 8 pad, 144B)
#define SCALE 0.125f      // 1/sqrt(64)
#define NKT (Sc / TK)     // 32
#define FM_BLOCKS 4096    // prep: fm portion of the merged grid

// g_fmp (uint4): (((b*16+qt)*32+kt)*8 + p)*128 + part*32 + lane
//   slot p covers q-rows p*16..p*16+15 of the tile; part0/1 = lo-row cols 0-31/32-63,
//   part2/3 = hi-row (g+8) cols 0-31/32-63
__device__ __align__(16) uint4 g_fmp[(size_t)Bc * 16 * 32 * 8 * 128];
__device__ __align__(16) __half g_kh[(size_t)Bc * Hc * Sc * Dc];
__device__ __align__(16) __half g_vh[(size_t)Bc * Hc * Sc * Dc];
__device__ __align__(16) unsigned g_ps[(size_t)Bc * Hc * Sc * Sc / 2];  // 201 MB

// merged prep: blocks [0,4096) build FM fragments; the rest convert K/V to fp16
__global__ void prep_kernel(const float* __restrict__ freq,
                            const int*  __restrict__ mask,
                            const float* __restrict__ K,
                            const float* __restrict__ V) {
    if (blockIdx.x < FM_BLOCKS) {
        unsigned idx = blockIdx.x * blockDim.x + threadIdx.x;   // one uint4 out
        int lane = idx & 31, part = (idx >> 5) & 3, p = (idx >> 7) & 7;
        int kt = (idx >> 10) & 31, qt = (idx >> 15) & 15, b = idx >> 19;
        int g = lane >> 2, tg = lane & 3;
        int q = qt * TQ + p * 16 + g + ((part >> 1) << 3);
        const float* fr = freq + ((size_t)b * Sc + q) * Sc;
        const int*   mr = mask + ((size_t)b * Sc + q) * Sc;
        int kbase = kt * 64 + (part & 1) * 32 + tg * 2;
        unsigned out[4];
        #pragma unroll
        for (int j = 0; j < 4; ++j) {
            int k = kbase + j * 8;
            float2 f = *(const float2*)(fr + k);
            int2   m = *(const int2*)(mr + k);
            __half2 h = __floats2half2_rn(m.x ? __logf(f.x) : -60000.0f,
                                          m.y ? __logf(f.y) : -60000.0f);
            out[j] = *(unsigned*)&h;
        }
        g_fmp[idx] = make_uint4(out[0], out[1], out[2], out[3]);
    } else {
        size_t base = ((size_t)(blockIdx.x - FM_BLOCKS) * blockDim.x + threadIdx.x) * 8;
        float4 a = *(const float4*)(K + base);
        float4 b4 = *(const float4*)(K + base + 4);
        __half2 h0 = __floats2half2_rn(a.x, a.y), h1 = __floats2half2_rn(a.z, a.w);
        __half2 h2 = __floats2half2_rn(b4.x, b4.y), h3 = __floats2half2_rn(b4.z, b4.w);
        uint4 u;
        u.x = *(unsigned*)&h0; u.y = *(unsigned*)&h1;
        u.z = *(unsigned*)&h2; u.w = *(unsigned*)&h3;
        *(uint4*)(g_kh + base) = u;
        a = *(const float4*)(V + base);
        b4 = *(const float4*)(V + base + 4);
        h0 = __floats2half2_rn(a.x, a.y); h1 = __floats2half2_rn(a.z, a.w);
        h2 = __floats2half2_rn(b4.x, b4.y); h3 = __floats2half2_rn(b4.z, b4.w);
        u.x = *(unsigned*)&h0; u.y = *(unsigned*)&h1;
        u.z = *(unsigned*)&h2; u.w = *(unsigned*)&h3;
        *(uint4*)(g_vh + base) = u;
    }
}

__device__ __forceinline__ void mma_f16(float* c, const unsigned* a, const unsigned* b) {
    asm volatile(
        "mma.sync.aligned.m16n8k16.row.col.f32.f16.f16.f32 "
        "{%0,%1,%2,%3}, {%4,%5,%6,%7}, {%8,%9}, {%0,%1,%2,%3};\n"
        : "+f"(c[0]), "+f"(c[1]), "+f"(c[2]), "+f"(c[3])
        : "r"(a[0]), "r"(a[1]), "r"(a[2]), "r"(a[3]), "r"(b[0]), "r"(b[1]));
}

__device__ __forceinline__ void ldsm4(unsigned& r0, unsigned& r1, unsigned& r2,
                                      unsigned& r3, unsigned addr) {
    asm volatile("ldmatrix.sync.aligned.m8n8.x4.shared.b16 {%0,%1,%2,%3}, [%4];"
                 : "=r"(r0), "=r"(r1), "=r"(r2), "=r"(r3) : "r"(addr));
}

__device__ __forceinline__ void ldsm4t(unsigned& r0, unsigned& r1, unsigned& r2,
                                       unsigned& r3, unsigned addr) {
    asm volatile("ldmatrix.sync.aligned.m8n8.x4.trans.shared.b16 {%0,%1,%2,%3}, [%4];"
                 : "=r"(r0), "=r"(r1), "=r"(r2), "=r"(r3) : "r"(addr));
}

__global__ void __launch_bounds__(NTH, 2)
attn_kernel(const float* __restrict__ Q, float* __restrict__ Out,
            float* __restrict__ Pout, int writep) {
    // Ks | Vs (64 x STRD each); Q prologue overlays both (128 x STRD)
    __shared__ __align__(16) __half smem_buf[2 * TK * STRD];
    __half* Ks = smem_buf;
    __half* Vs = smem_buf + TK * STRD;

    const int tid = threadIdx.x;
    const int w = tid >> 5, lane = tid & 31;      // w = 0..7
    const int g = lane >> 2, tg = lane & 3;
    const int wq = w * 16;                        // warp's 16-row base
    const int h = blockIdx.x, qt = blockIdx.y, b = blockIdx.z;
    const int q0 = qt * TQ;

    const size_t bh = (size_t)b * Hc + h;
    const float*  Qg = Q + (bh * Sc + q0) * Dc;
    const __half* Kh = g_kh + bh * Sc * Dc;
    const __half* Vh = g_vh + bh * Sc * Dc;
    float* Og = Out + (bh * Sc + q0) * Dc;
    float* Pg = Pout + (bh * Sc + q0) * Sc;

    // FM fragments: slot p = w (this warp's 16 rows); per-kt stride 8*128 uint4
    const uint4* fmb = g_fmp +
                 ((((size_t)b * 16 + qt) * NKT) * 8 + w) * 128 + lane;
    // scratch exp fragments: same slot algebra, per (b,h)
    uint4* scr = (uint4*)g_ps +
                 ((((bh * (Sc / TQ) + qt) * NKT) * 8 + w)) * 128 + lane;

    const unsigned smem_u = (unsigned)__cvta_generic_to_shared(smem_buf);
    const unsigned vs_u   = smem_u + TK * STRD * 2;
    // B (K): m0=(n0-7,klo) m1=(n0-7,khi) m2=(n8-15,klo) m3=(n8-15,khi)
    const int brow = ((lane >> 4) & 1) * 8 + (lane & 7);
    const int bcol = ((lane >> 3) & 1) * 8;
    const unsigned addrB = smem_u + ((brow * STRD + bcol) << 1);
    // V (trans)
    const int vrow = ((lane >> 3) & 1) * 8 + (lane & 7);
    const int vcol = ((lane >> 4) & 1) * 8;
    const unsigned addrV = vs_u + ((vrow * STRD + vcol) << 1);

    // ---- Q prologue: stage fp32->fp16 (all 128 rows), load A-fragments ----
    #pragma unroll
    for (int i = tid; i < TQ * 16; i += NTH) {
        int r = i >> 4, c = (i & 15) * 4;
        float4 v = *(const float4*)(Qg + (size_t)r * Dc + c);
        __half2 p0 = __floats2half2_rn(v.x, v.y), p1 = __floats2half2_rn(v.z, v.w);
        uint2 u; u.x = *(unsigned*)&p0; u.y = *(unsigned*)&p1;
        *(uint2*)(smem_buf + r * STRD + c) = u;
    }
    __syncthreads();
    unsigned qa[4][4];
    {
        unsigned addrA = smem_u +
            (((wq + (lane & 15)) * STRD + (lane >> 4) * 8) << 1);
        #pragma unroll
        for (int ks = 0; ks < 4; ++ks)
            ldsm4(qa[ks][0], qa[ks][1], qa[ks][2], qa[ks][3], addrA + ks * 32);
    }

    // ---------------- pass 1: scores -> exp fragments + Z ----------------
    float z0 = 0.0f, z1 = 0.0f;
    for (int kt = 0; kt < NKT; ++kt) {
        // FM fragment loads issued early (independent of smem)
        const uint4* fp = fmb + (size_t)kt * 8 * 128;
        uint4 fm0 = fp[0], fm1 = fp[32], fm2 = fp[64], fm3 = fp[96];

        __syncthreads();
        #pragma unroll
        for (int i = tid; i < TK * 8; i += NTH) {      // K tile (uint4 copy)
            int r = i >> 3, c = (i & 7) * 8;
            *(uint4*)(Ks + r * STRD + c) =
                *(const uint4*)(Kh + (size_t)(kt * TK + r) * Dc + c);
        }
        __syncthreads();

        float sacc[8][4];
        #pragma unroll
        for (int nt = 0; nt < 8; ++nt)
            sacc[nt][0] = sacc[nt][1] = sacc[nt][2] = sacc[nt][3] = 0.0f;

        #pragma unroll
        for (int ks = 0; ks < 4; ++ks) {
            #pragma unroll
            for (int ntp = 0; ntp < 4; ++ntp) {
                unsigned b0, b1, b2, b3;
                ldsm4(b0, b1, b2, b3, addrB + (ntp * 16 * STRD + ks * 16) * 2);
                unsigned blo[2] = {b0, b1}, bhi[2] = {b2, b3};
                mma_f16(sacc[2 * ntp],     qa[ks], blo);
                mma_f16(sacc[2 * ntp + 1], qa[ks], bhi);
            }
        }

        // exp with FM registers; store unnormalized fp16 exp fragments
        unsigned sl[8], sh[8];
        #pragma unroll
        for (int nt = 0; nt < 8; ++nt) {
            unsigned flo_u = (nt < 4) ? ((const unsigned*)&fm0)[nt & 3]
                                      : ((const unsigned*)&fm1)[nt & 3];
            unsigned fhi_u = (nt < 4) ? ((const unsigned*)&fm2)[nt & 3]
                                      : ((const unsigned*)&fm3)[nt & 3];
            float2 flo = __half22float2(*(__half2*)&flo_u);
            float2 fhi = __half22float2(*(__half2*)&fhi_u);
            float p0 = __expf(fmaf(sacc[nt][0], SCALE, flo.x));
            float p1 = __expf(fmaf(sacc[nt][1], SCALE, flo.y));
            float p2 = __expf(fmaf(sacc[nt][2], SCALE, fhi.x));
            float p3 = __expf(fmaf(sacc[nt][3], SCALE, fhi.y));
            z0 += p0 + p1;
            z1 += p2 + p3;
            __half2 hlo = __floats2half2_rn(p0, p1);
            __half2 hhi = __floats2half2_rn(p2, p3);
            sl[nt] = *(unsigned*)&hlo;
            sh[nt] = *(unsigned*)&hhi;
        }
        uint4* sp = scr + (size_t)kt * 8 * 128;
        sp[0]  = make_uint4(sl[0], sl[1], sl[2], sl[3]);
        sp[32] = make_uint4(sl[4], sl[5], sl[6], sl[7]);
        sp[64] = make_uint4(sh[0], sh[1], sh[2], sh[3]);
        sp[96] = make_uint4(sh[4], sh[5], sh[6], sh[7]);
    }
    z0 += __shfl_xor_sync(0xffffffffu, z0, 1);
    z0 += __shfl_xor_sync(0xffffffffu, z0, 2);
    z1 += __shfl_xor_sync(0xffffffffu, z1, 1);
    z1 += __shfl_xor_sync(0xffffffffu, z1, 2);
    const float iz0 = 1.0f / z0;
    const float iz1 = 1.0f / z1;

    // ---------------- pass 2: normalize P + PV (no QK recompute) ----------------
    float oacc[8][4];
    #pragma unroll
    for (int nt = 0; nt < 8; ++nt)
        oacc[nt][0] = oacc[nt][1] = oacc[nt][2] = oacc[nt][3] = 0.0f;

    float2* Pp0 = (float2*)(Pg + (size_t)(wq + g) * Sc) + tg;
    float2* Pp1 = (float2*)(Pg + (size_t)(wq + g + 8) * Sc) + tg;

    for (int kt = 0; kt < NKT; ++kt) {
        // scratch readback issued early (independent of smem)
        uint4* sp = scr + (size_t)kt * 8 * 128;
        uint4 a0 = sp[0], a1 = sp[32], a2 = sp[64], a3 = sp[96];
        unsigned sl[8], sh[8];
        sl[0] = a0.x; sl[1] = a0.y; sl[2] = a0.z; sl[3] = a0.w;
        sl[4] = a1.x; sl[5] = a1.y; sl[6] = a1.z; sl[7] = a1.w;
        sh[0] = a2.x; sh[1] = a2.y; sh[2] = a2.z; sh[3] = a2.w;
        sh[4] = a3.x; sh[5] = a3.y; sh[6] = a3.z; sh[7] = a3.w;

        __syncthreads();
        #pragma unroll
        for (int i = tid; i < TK * 8; i += NTH) {      // V tile (uint4 copy)
            int r = i >> 3, c = (i & 7) * 8;
            *(uint4*)(Vs + r * STRD + c) =
                *(const uint4*)(Vh + (size_t)(kt * TK + r) * Dc + c);
        }
        __syncthreads();

        // emit normalized fp32 P
        if (writep) {
            #pragma unroll
            for (int nt = 0; nt < 8; ++nt) {
                float2 plo = __half22float2(*(__half2*)&sl[nt]);
                float2 phi = __half22float2(*(__half2*)&sh[nt]);
                __stwt(Pp0 + kt * 32 + nt * 4,
                       make_float2(plo.x * iz0, plo.y * iz0));
                __stwt(Pp1 + kt * 32 + nt * 4,
                       make_float2(phi.x * iz1, phi.y * iz1));
            }
        }

        // PV with unnormalized fp16 fragments (scale at the end)
        #pragma unroll
        for (int ks2 = 0; ks2 < 4; ++ks2) {
            unsigned a[4] = {sl[2 * ks2], sh[2 * ks2],
                             sl[2 * ks2 + 1], sh[2 * ks2 + 1]};
            #pragma unroll
            for (int ntp = 0; ntp < 4; ++ntp) {
                unsigned v0, v1, v2, v3;
                ldsm4t(v0, v1, v2, v3, addrV + (ks2 * 16 * STRD + ntp * 16) * 2);
                unsigned blo[2] = {v0, v1}, bhi[2] = {v2, v3};
                mma_f16(oacc[2 * ntp],     a, blo);
                mma_f16(oacc[2 * ntp + 1], a, bhi);
            }
        }
    }

    // scale by 1/Z and write O tile
    {
        float* o0 = Og + (size_t)(wq + g) * Dc;
        float* o1 = Og + (size_t)(wq + g + 8) * Dc;
        #pragma unroll
        for (int nt = 0; nt < 8; ++nt) {
            int col = nt * 8 + 2 * tg;
            *(float2*)(o0 + col) = make_float2(oacc[nt][0] * iz0,
                                               oacc[nt][1] * iz0);
            *(float2*)(o1 + col) = make_float2(oacc[nt][2] * iz1,
                                               oacc[nt][3] * iz1);
        }
    }
}

extern "C" void kernel_launch(void* const* d_in, const int* in_sizes, int n_in,
                              void* d_out, int out_size) {
    const float* Q    = (const float*)d_in[0];
    const float* K    = (const float*)d_in[1];
    const float* V    = (const float*)d_in[2];
    const float* freq = (const float*)d_in[3];
    const int*   mask = (const int*)d_in[4];

    const size_t out_elems = (size_t)Bc * Hc * Sc * Dc;   // 3,145,728
    float* Out  = (float*)d_out;
    float* Pout = (float*)d_out + out_elems;              // p_attn follows out
    int writep  = (out_size > (int)out_elems) ? 1 : 0;

    {
        // fm: 2^20 threads / 256 = 4096 blocks; kv: 3.1M/8/256 = 1536 blocks
        int kv_blocks = (Bc * Hc * Sc * Dc) / (256 * 8);
        prep_kernel<<<FM_BLOCKS + kv_blocks, 256>>>(freq, mask, K, V);
    }
    {
        dim3 grid(Hc, Sc / TQ, Bc);
        attn_kernel<<<grid, NTH>>>(Q, Out, Pout, writep);
    }
}

// round 16
// speedup vs baseline: 1.2094x; 1.0860x over previous
#include <cuda_runtime.h>
#include <cuda_fp16.h>

#define Bc 2
#define Hc 12
#define Sc 2048
#define Dc 64
#define TQ 128
#define TK 64
#define NTH 128
#define STRD 72           // smem row stride in halves (64 + 8 pad, 144B)
#define BUFB (TK * STRD * 2)   // bytes per K/V buffer
#define SCALE 0.125f      // 1/sqrt(64)
#define NKT (Sc / TK)     // 32
#define FM_BLOCKS 4096

// g_fmp (uint4): (((b*16+qt)*32+kt)*8 + p)*128 + part*32 + lane ; p=w*2+mb
__device__ __align__(16) uint4 g_fmp[(size_t)Bc * 16 * 32 * 8 * 128];
__device__ __align__(16) __half g_kh[(size_t)Bc * Hc * Sc * Dc];
__device__ __align__(16) __half g_vh[(size_t)Bc * Hc * Sc * Dc];
__device__ __align__(16) unsigned g_ps[(size_t)Bc * Hc * Sc * Sc / 2];  // 201 MB

// merged prep: blocks [0,4096) build FM fragments; the rest convert K/V to fp16
__global__ void prep_kernel(const float* __restrict__ freq,
                            const int*  __restrict__ mask,
                            const float* __restrict__ K,
                            const float* __restrict__ V) {
    if (blockIdx.x < FM_BLOCKS) {
        unsigned idx = blockIdx.x * blockDim.x + threadIdx.x;   // one uint4 out
        int lane = idx & 31, part = (idx >> 5) & 3, p = (idx >> 7) & 7;
        int kt = (idx >> 10) & 31, qt = (idx >> 15) & 15, b = idx >> 19;
        int g = lane >> 2, tg = lane & 3;
        int q = qt * TQ + p * 16 + g + ((part >> 1) << 3);
        const float* fr = freq + ((size_t)b * Sc + q) * Sc;
        const int*   mr = mask + ((size_t)b * Sc + q) * Sc;
        int kbase = kt * 64 + (part & 1) * 32 + tg * 2;
        unsigned out[4];
        #pragma unroll
        for (int j = 0; j < 4; ++j) {
            int k = kbase + j * 8;
            float2 f = *(const float2*)(fr + k);
            int2   m = *(const int2*)(mr + k);
            __half2 h = __floats2half2_rn(m.x ? __logf(f.x) : -60000.0f,
                                          m.y ? __logf(f.y) : -60000.0f);
            out[j] = *(unsigned*)&h;
        }
        g_fmp[idx] = make_uint4(out[0], out[1], out[2], out[3]);
    } else {
        size_t base = ((size_t)(blockIdx.x - FM_BLOCKS) * blockDim.x + threadIdx.x) * 8;
        float4 a = *(const float4*)(K + base);
        float4 b4 = *(const float4*)(K + base + 4);
        __half2 h0 = __floats2half2_rn(a.x, a.y), h1 = __floats2half2_rn(a.z, a.w);
        __half2 h2 = __floats2half2_rn(b4.x, b4.y), h3 = __floats2half2_rn(b4.z, b4.w);
        uint4 u;
        u.x = *(unsigned*)&h0; u.y = *(unsigned*)&h1;
        u.z = *(unsigned*)&h2; u.w = *(unsigned*)&h3;
        *(uint4*)(g_kh + base) = u;
        a = *(const float4*)(V + base);
        b4 = *(const float4*)(V + base + 4);
        h0 = __floats2half2_rn(a.x, a.y); h1 = __floats2half2_rn(a.z, a.w);
        h2 = __floats2half2_rn(b4.x, b4.y); h3 = __floats2half2_rn(b4.z, b4.w);
        u.x = *(unsigned*)&h0; u.y = *(unsigned*)&h1;
        u.z = *(unsigned*)&h2; u.w = *(unsigned*)&h3;
        *(uint4*)(g_vh + base) = u;
    }
}

__device__ __forceinline__ void mma_f16(float* c, const unsigned* a, const unsigned* b) {
    asm volatile(
        "mma.sync.aligned.m16n8k16.row.col.f32.f16.f16.f32 "
        "{%0,%1,%2,%3}, {%4,%5,%6,%7}, {%8,%9}, {%0,%1,%2,%3};\n"
        : "+f"(c[0]), "+f"(c[1]), "+f"(c[2]), "+f"(c[3])
        : "r"(a[0]), "r"(a[1]), "r"(a[2]), "r"(a[3]), "r"(b[0]), "r"(b[1]));
}

__device__ __forceinline__ void ldsm4(unsigned& r0, unsigned& r1, unsigned& r2,
                                      unsigned& r3, unsigned addr) {
    asm volatile("ldmatrix.sync.aligned.m8n8.x4.shared.b16 {%0,%1,%2,%3}, [%4];"
                 : "=r"(r0), "=r"(r1), "=r"(r2), "=r"(r3) : "r"(addr));
}

__device__ __forceinline__ void ldsm4t(unsigned& r0, unsigned& r1, unsigned& r2,
                                       unsigned& r3, unsigned addr) {
    asm volatile("ldmatrix.sync.aligned.m8n8.x4.trans.shared.b16 {%0,%1,%2,%3}, [%4];"
                 : "=r"(r0), "=r"(r1), "=r"(r2), "=r"(r3) : "r"(addr));
}

__global__ void __launch_bounds__(NTH)
attn_kernel(const float* __restrict__ Q, float* __restrict__ Out,
            float* __restrict__ Pout, int writep) {
    // two 64xSTRD fp16 buffers (K pass1 / V pass2); Q prologue overlays both
    __shared__ __align__(16) __half smem_buf[2 * TK * STRD];

    const int tid = threadIdx.x;
    const int w = tid >> 5, lane = tid & 31;
    const int g = lane >> 2, tg = lane & 3;
    const int wq = w * 32;
    const int h = blockIdx.x, qt = blockIdx.y, b = blockIdx.z;
    const int q0 = qt * TQ;

    const size_t bh = (size_t)b * Hc + h;
    const float*  Qg = Q + (bh * Sc + q0) * Dc;
    const __half* Kh = g_kh + bh * Sc * Dc;
    const __half* Vh = g_vh + bh * Sc * Dc;
    float* Og = Out + (bh * Sc + q0) * Dc;
    float* Pg = Pout + (bh * Sc + q0) * Sc;

    // FM fragments (h-independent); slot p = w*2+mb
    const uint4* fmb = g_fmp +
                 ((((size_t)b * 16 + qt) * NKT) * 8 + w * 2) * 128 + lane;
    // scratch exp fragments (R12 layout)
    uint4* scr = (uint4*)g_ps +
                 ((((bh * (Sc / TQ) + qt) * NKT) * 4 + w) * 2) * 128 + lane;

    const unsigned smem_u = (unsigned)__cvta_generic_to_shared(smem_buf);
    // B (K): m0=(n0-7,klo) m1=(n0-7,khi) m2=(n8-15,klo) m3=(n8-15,khi)
    const int brow = ((lane >> 4) & 1) * 8 + (lane & 7);
    const int bcol = ((lane >> 3) & 1) * 8;
    const unsigned addrB = smem_u + ((brow * STRD + bcol) << 1);
    // V (trans)
    const int vrow = ((lane >> 3) & 1) * 8 + (lane & 7);
    const int vcol = ((lane >> 4) & 1) * 8;
    const unsigned addrV = smem_u + ((vrow * STRD + vcol) << 1);

    // per-thread staging slot: 4 uint4 per thread per tile
    int strow[4], stcol[4];
    #pragma unroll
    for (int t = 0; t < 4; ++t) {
        int idx = tid + t * NTH;
        strow[t] = idx >> 3;
        stcol[t] = (idx & 7) * 8;
    }

    // ---- Q prologue: stage fp32->fp16 (all 128 rows), load A-fragments ----
    #pragma unroll
    for (int i = tid; i < TQ * 16; i += NTH) {
        int r = i >> 4, c = (i & 15) * 4;
        float4 v = *(const float4*)(Qg + (size_t)r * Dc + c);
        __half2 p0 = __floats2half2_rn(v.x, v.y), p1 = __floats2half2_rn(v.z, v.w);
        uint2 u; u.x = *(unsigned*)&p0; u.y = *(unsigned*)&p1;
        *(uint2*)(smem_buf + r * STRD + c) = u;
    }
    __syncthreads();
    unsigned qa[2][4][4];
    #pragma unroll
    for (int mb = 0; mb < 2; ++mb) {
        unsigned addrA = smem_u +
            (((wq + 16 * mb + (lane & 15)) * STRD + (lane >> 4) * 8) << 1);
        #pragma unroll
        for (int ks = 0; ks < 4; ++ks)
            ldsm4(qa[mb][ks][0], qa[mb][ks][1], qa[mb][ks][2], qa[mb][ks][3],
                  addrA + ks * 32);
    }
    __syncthreads();          // all qa ldsm done before K tile 0 overwrites smem

    // ---------------- pass 1: scores -> exp fragments + Z ----------------
    // prologue: stage K tile 0 into buf0
    #pragma unroll
    for (int t = 0; t < 4; ++t)
        *(uint4*)(smem_buf + strow[t] * STRD + stcol[t]) =
            *(const uint4*)(Kh + (size_t)strow[t] * Dc + stcol[t]);

    float z[2][2] = {{0.0f, 0.0f}, {0.0f, 0.0f}};
    for (int kt = 0; kt < NKT; ++kt) {
        // FM fragment loads issued early (independent of smem)
        uint4 fm[2][4];
        #pragma unroll
        for (int mb = 0; mb < 2; ++mb) {
            const uint4* fp = fmb + ((size_t)kt * 8 + mb) * 128;
            fm[mb][0] = fp[0];  fm[mb][1] = fp[32];
            fm[mb][2] = fp[64]; fm[mb][3] = fp[96];
        }

        __syncthreads();                       // buf[kt&1] visible
        // prefetch next K tile into registers (latency hidden by mma below)
        uint4 nxt[4];
        if (kt + 1 < NKT) {
            const __half* src = Kh + (size_t)(kt + 1) * TK * Dc;
            #pragma unroll
            for (int t = 0; t < 4; ++t)
                nxt[t] = *(const uint4*)(src + (size_t)strow[t] * Dc + stcol[t]);
        }

        const unsigned aB = addrB + (kt & 1) * BUFB;
        float sacc[2][8][4];
        #pragma unroll
        for (int mb = 0; mb < 2; ++mb)
            #pragma unroll
            for (int nt = 0; nt < 8; ++nt)
                sacc[mb][nt][0] = sacc[mb][nt][1] = sacc[mb][nt][2] = sacc[mb][nt][3] = 0.0f;

        #pragma unroll
        for (int ks = 0; ks < 4; ++ks) {
            unsigned bf[4][4];
            #pragma unroll
            for (int ntp = 0; ntp < 4; ++ntp)
                ldsm4(bf[ntp][0], bf[ntp][1], bf[ntp][2], bf[ntp][3],
                      aB + (ntp * 16 * STRD + ks * 16) * 2);
            #pragma unroll
            for (int mb = 0; mb < 2; ++mb)
                #pragma unroll
                for (int ntp = 0; ntp < 4; ++ntp) {
                    mma_f16(sacc[mb][2 * ntp],     qa[mb][ks], &bf[ntp][0]);
                    mma_f16(sacc[mb][2 * ntp + 1], qa[mb][ks], &bf[ntp][2]);
                }
        }

        // stage prefetched tile into the other buffer (visible at next sync)
        if (kt + 1 < NKT) {
            __half* dst = smem_buf + ((kt + 1) & 1) * (TK * STRD);
            #pragma unroll
            for (int t = 0; t < 4; ++t)
                *(uint4*)(dst + strow[t] * STRD + stcol[t]) = nxt[t];
        }

        // exp with FM registers; store unnormalized fp16 exp fragments
        #pragma unroll
        for (int mb = 0; mb < 2; ++mb) {
            unsigned sl[8], sh[8];
            #pragma unroll
            for (int nt = 0; nt < 8; ++nt) {
                unsigned flo_u = ((const unsigned*)&fm[mb][nt >> 2])[nt & 3];
                unsigned fhi_u = ((const unsigned*)&fm[mb][2 + (nt >> 2)])[nt & 3];
                float2 flo = __half22float2(*(__half2*)&flo_u);
                float2 fhi = __half22float2(*(__half2*)&fhi_u);
                float p0 = __expf(fmaf(sacc[mb][nt][0], SCALE, flo.x));
                float p1 = __expf(fmaf(sacc[mb][nt][1], SCALE, flo.y));
                float p2 = __expf(fmaf(sacc[mb][nt][2], SCALE, fhi.x));
                float p3 = __expf(fmaf(sacc[mb][nt][3], SCALE, fhi.y));
                z[mb][0] += p0 + p1;
                z[mb][1] += p2 + p3;
                __half2 hlo = __floats2half2_rn(p0, p1);
                __half2 hhi = __floats2half2_rn(p2, p3);
                sl[nt] = *(unsigned*)&hlo;
                sh[nt] = *(unsigned*)&hhi;
            }
            uint4* sp = scr + ((size_t)kt * 8 + mb) * 128;
            sp[0]  = make_uint4(sl[0], sl[1], sl[2], sl[3]);
            sp[32] = make_uint4(sl[4], sl[5], sl[6], sl[7]);
            sp[64] = make_uint4(sh[0], sh[1], sh[2], sh[3]);
            sp[96] = make_uint4(sh[4], sh[5], sh[6], sh[7]);
        }
    }
    float iz[2][2];
    #pragma unroll
    for (int mb = 0; mb < 2; ++mb)
        #pragma unroll
        for (int hf = 0; hf < 2; ++hf) {
            float zz = z[mb][hf];
            zz += __shfl_xor_sync(0xffffffffu, zz, 1);
            zz += __shfl_xor_sync(0xffffffffu, zz, 2);
            iz[mb][hf] = 1.0f / zz;
        }

    // ---------------- pass 2: normalize P + PV ----------------
    float oacc[2][8][4];
    #pragma unroll
    for (int mb = 0; mb < 2; ++mb)
        #pragma unroll
        for (int nt = 0; nt < 8; ++nt)
            oacc[mb][nt][0] = oacc[mb][nt][1] = oacc[mb][nt][2] = oacc[mb][nt][3] = 0.0f;

    float2* Pp[2][2];
    #pragma unroll
    for (int mb = 0; mb < 2; ++mb) {
        Pp[mb][0] = (float2*)(Pg + (size_t)(wq + 16 * mb + g) * Sc) + tg;
        Pp[mb][1] = (float2*)(Pg + (size_t)(wq + 16 * mb + g + 8) * Sc) + tg;
    }

    // prologue: stage V tile 0 into buf0 (pass1's last reads were buf1)
    #pragma unroll
    for (int t = 0; t < 4; ++t)
        *(uint4*)(smem_buf + strow[t] * STRD + stcol[t]) =
            *(const uint4*)(Vh + (size_t)strow[t] * Dc + stcol[t]);

    for (int kt = 0; kt < NKT; ++kt) {
        // scratch readback issued early (independent of smem)
        unsigned sl[2][8], sh[2][8];
        #pragma unroll
        for (int mb = 0; mb < 2; ++mb) {
            uint4* sp = scr + ((size_t)kt * 8 + mb) * 128;
            uint4 a0 = sp[0], a1 = sp[32], a2 = sp[64], a3 = sp[96];
            sl[mb][0] = a0.x; sl[mb][1] = a0.y; sl[mb][2] = a0.z; sl[mb][3] = a0.w;
            sl[mb][4] = a1.x; sl[mb][5] = a1.y; sl[mb][6] = a1.z; sl[mb][7] = a1.w;
            sh[mb][0] = a2.x; sh[mb][1] = a2.y; sh[mb][2] = a2.z; sh[mb][3] = a2.w;
            sh[mb][4] = a3.x; sh[mb][5] = a3.y; sh[mb][6] = a3.z; sh[mb][7] = a3.w;
        }

        __syncthreads();                       // buf[kt&1] visible
        uint4 nxt[4];
        if (kt + 1 < NKT) {
            const __half* src = Vh + (size_t)(kt + 1) * TK * Dc;
            #pragma unroll
            for (int t = 0; t < 4; ++t)
                nxt[t] = *(const uint4*)(src + (size_t)strow[t] * Dc + stcol[t]);
        }

        // emit normalized fp32 P
        if (writep) {
            #pragma unroll
            for (int mb = 0; mb < 2; ++mb)
                #pragma unroll
                for (int nt = 0; nt < 8; ++nt) {
                    float2 plo = __half22float2(*(__half2*)&sl[mb][nt]);
                    float2 phi = __half22float2(*(__half2*)&sh[mb][nt]);
                    __stwt(Pp[mb][0] + kt * 32 + nt * 4,
                           make_float2(plo.x * iz[mb][0], plo.y * iz[mb][0]));
                    __stwt(Pp[mb][1] + kt * 32 + nt * 4,
                           make_float2(phi.x * iz[mb][1], phi.y * iz[mb][1]));
                }
        }

        // PV with unnormalized fp16 fragments (scale at the end)
        const unsigned aV = addrV + (kt & 1) * BUFB;
        #pragma unroll
        for (int ks2 = 0; ks2 < 4; ++ks2) {
            #pragma unroll
            for (int ntp = 0; ntp < 4; ++ntp) {
                unsigned v0, v1, v2, v3;
                ldsm4t(v0, v1, v2, v3, aV + (ks2 * 16 * STRD + ntp * 16) * 2);
                unsigned blo[2] = {v0, v1}, bhi[2] = {v2, v3};
                #pragma unroll
                for (int mb = 0; mb < 2; ++mb) {
                    unsigned a[4] = {sl[mb][2 * ks2], sh[mb][2 * ks2],
                                     sl[mb][2 * ks2 + 1], sh[mb][2 * ks2 + 1]};
                    mma_f16(oacc[mb][2 * ntp],     a, blo);
                    mma_f16(oacc[mb][2 * ntp + 1], a, bhi);
                }
            }
        }

        // stage prefetched V tile into the other buffer
        if (kt + 1 < NKT) {
            __half* dst = smem_buf + ((kt + 1) & 1) * (TK * STRD);
            #pragma unroll
            for (int t = 0; t < 4; ++t)
                *(uint4*)(dst + strow[t] * STRD + stcol[t]) = nxt[t];
        }
    }

    // scale by 1/Z and write O tile
    #pragma unroll
    for (int mb = 0; mb < 2; ++mb) {
        float* o0 = Og + (size_t)(wq + 16 * mb + g) * Dc;
        float* o1 = Og + (size_t)(wq + 16 * mb + g + 8) * Dc;
        #pragma unroll
        for (int nt = 0; nt < 8; ++nt) {
            int col = nt * 8 + 2 * tg;
            *(float2*)(o0 + col) = make_float2(oacc[mb][nt][0] * iz[mb][0],
                                               oacc[mb][nt][1] * iz[mb][0]);
            *(float2*)(o1 + col) = make_float2(oacc[mb][nt][2] * iz[mb][1],
                                               oacc[mb][nt][3] * iz[mb][1]);
        }
    }
}

extern "C" void kernel_launch(void* const* d_in, const int* in_sizes, int n_in,
                              void* d_out, int out_size) {
    const float* Q    = (const float*)d_in[0];
    const float* K    = (const float*)d_in[1];
    const float* V    = (const float*)d_in[2];
    const float* freq = (const float*)d_in[3];
    const int*   mask = (const int*)d_in[4];

    const size_t out_elems = (size_t)Bc * Hc * Sc * Dc;   // 3,145,728
    float* Out  = (float*)d_out;
    float* Pout = (float*)d_out + out_elems;              // p_attn follows out
    int writep  = (out_size > (int)out_elems) ? 1 : 0;

    {
        int kv_blocks = (Bc * Hc * Sc * Dc) / (256 * 8);
        prep_kernel<<<FM_BLOCKS + kv_blocks, 256>>>(freq, mask, K, V);
    }
    {
        dim3 grid(Hc, Sc / TQ, Bc);
        attn_kernel<<<grid, NTH>>>(Q, Out, Pout, writep);
    }
}

// round 17
// speedup vs baseline: 1.5457x; 1.2781x over previous
#include <cuda_runtime.h>
#include <cuda_fp16.h>

#define Bc 2
#define Hc 12
#define Sc 2048
#define Dc 64
#define TQ 128
#define TK 64
#define NTH 128
#define STRD 72           // smem row stride in halves (64 + 8 pad, 144B)
#define SCALE 0.125f      // 1/sqrt(64)
#define NKT (Sc / TK)     // 32
#define FM_BLOCKS 4096

// g_fmp (uint4): (((b*16+qt)*32+kt)*8 + p)*128 + part*32 + lane ; p=w*2+mb
__device__ __align__(16) uint4 g_fmp[(size_t)Bc * 16 * 32 * 8 * 128];
__device__ __align__(16) __half g_kh[(size_t)Bc * Hc * Sc * Dc];
__device__ __align__(16) __half g_vh[(size_t)Bc * Hc * Sc * Dc];
__device__ __align__(16) unsigned g_ps[(size_t)Bc * Hc * Sc * Sc / 2];  // 201 MB

// merged prep: blocks [0,4096) build FM fragments; the rest convert K/V to fp16
__global__ void prep_kernel(const float* __restrict__ freq,
                            const int*  __restrict__ mask,
                            const float* __restrict__ K,
                            const float* __restrict__ V) {
    if (blockIdx.x < FM_BLOCKS) {
        unsigned idx = blockIdx.x * blockDim.x + threadIdx.x;   // one uint4 out
        int lane = idx & 31, part = (idx >> 5) & 3, p = (idx >> 7) & 7;
        int kt = (idx >> 10) & 31, qt = (idx >> 15) & 15, b = idx >> 19;
        int g = lane >> 2, tg = lane & 3;
        int q = qt * TQ + p * 16 + g + ((part >> 1) << 3);
        const float* fr = freq + ((size_t)b * Sc + q) * Sc;
        const int*   mr = mask + ((size_t)b * Sc + q) * Sc;
        int kbase = kt * 64 + (part & 1) * 32 + tg * 2;
        unsigned out[4];
        #pragma unroll
        for (int j = 0; j < 4; ++j) {
            int k = kbase + j * 8;
            float2 f = *(const float2*)(fr + k);
            int2   m = *(const int2*)(mr + k);
            __half2 h = __floats2half2_rn(m.x ? __logf(f.x) : -60000.0f,
                                          m.y ? __logf(f.y) : -60000.0f);
            out[j] = *(unsigned*)&h;
        }
        g_fmp[idx] = make_uint4(out[0], out[1], out[2], out[3]);
    } else {
        size_t base = ((size_t)(blockIdx.x - FM_BLOCKS) * blockDim.x + threadIdx.x) * 8;
        float4 a = *(const float4*)(K + base);
        float4 b4 = *(const float4*)(K + base + 4);
        __half2 h0 = __floats2half2_rn(a.x, a.y), h1 = __floats2half2_rn(a.z, a.w);
        __half2 h2 = __floats2half2_rn(b4.x, b4.y), h3 = __floats2half2_rn(b4.z, b4.w);
        uint4 u;
        u.x = *(unsigned*)&h0; u.y = *(unsigned*)&h1;
        u.z = *(unsigned*)&h2; u.w = *(unsigned*)&h3;
        *(uint4*)(g_kh + base) = u;
        a = *(const float4*)(V + base);
        b4 = *(const float4*)(V + base + 4);
        h0 = __floats2half2_rn(a.x, a.y); h1 = __floats2half2_rn(a.z, a.w);
        h2 = __floats2half2_rn(b4.x, b4.y); h3 = __floats2half2_rn(b4.z, b4.w);
        u.x = *(unsigned*)&h0; u.y = *(unsigned*)&h1;
        u.z = *(unsigned*)&h2; u.w = *(unsigned*)&h3;
        *(uint4*)(g_vh + base) = u;
    }
}

__device__ __forceinline__ void mma_f16(float* c, const unsigned* a, const unsigned* b) {
    asm volatile(
        "mma.sync.aligned.m16n8k16.row.col.f32.f16.f16.f32 "
        "{%0,%1,%2,%3}, {%4,%5,%6,%7}, {%8,%9}, {%0,%1,%2,%3};\n"
        : "+f"(c[0]), "+f"(c[1]), "+f"(c[2]), "+f"(c[3])
        : "r"(a[0]), "r"(a[1]), "r"(a[2]), "r"(a[3]), "r"(b[0]), "r"(b[1]));
}

__device__ __forceinline__ void ldsm4(unsigned& r0, unsigned& r1, unsigned& r2,
                                      unsigned& r3, unsigned addr) {
    asm volatile("ldmatrix.sync.aligned.m8n8.x4.shared.b16 {%0,%1,%2,%3}, [%4];"
                 : "=r"(r0), "=r"(r1), "=r"(r2), "=r"(r3) : "r"(addr));
}

__device__ __forceinline__ void ldsm4t(unsigned& r0, unsigned& r1, unsigned& r2,
                                       unsigned& r3, unsigned addr) {
    asm volatile("ldmatrix.sync.aligned.m8n8.x4.trans.shared.b16 {%0,%1,%2,%3}, [%4];"
                 : "=r"(r0), "=r"(r1), "=r"(r2), "=r"(r3) : "r"(addr));
}

__global__ void __launch_bounds__(NTH)
attn_kernel(const float* __restrict__ Q, float* __restrict__ Out,
            float* __restrict__ Pout, int writep) {
    // smem: Ks 64 | FM-dead | region reused: pass2 overlays Vs on Ks; Q staging transient
    __shared__ __align__(16) __half smem_buf[2 * TK * STRD];
    __half* Ks = smem_buf;                       // 64 x STRD (K pass1 / V pass2)

    const int tid = threadIdx.x;
    const int w = tid >> 5, lane = tid & 31;
    const int g = lane >> 2, tg = lane & 3;
    const int wq = w * 32;
    const int h = blockIdx.x, qt = blockIdx.y, b = blockIdx.z;
    const int q0 = qt * TQ;

    const size_t bh = (size_t)b * Hc + h;
    const float*  Qg = Q + (bh * Sc + q0) * Dc;
    const __half* Kh = g_kh + bh * Sc * Dc;
    const __half* Vh = g_vh + bh * Sc * Dc;
    float* Og = Out + (bh * Sc + q0) * Dc;
    float* Pg = Pout + (bh * Sc + q0) * Sc;

    // FM fragments (h-independent); slot p = w*2+mb
    const uint4* fmb = g_fmp +
                 ((((size_t)b * 16 + qt) * NKT) * 8 + w * 2) * 128 + lane;
    // scratch exp fragments (R12 layout)
    uint4* scr = (uint4*)g_ps +
                 ((((bh * (Sc / TQ) + qt) * NKT) * 4 + w) * 2) * 128 + lane;

    const unsigned smem_u = (unsigned)__cvta_generic_to_shared(smem_buf);
    // B (K): m0=(n0-7,klo) m1=(n0-7,khi) m2=(n8-15,klo) m3=(n8-15,khi)
    const int brow = ((lane >> 4) & 1) * 8 + (lane & 7);
    const int bcol = ((lane >> 3) & 1) * 8;
    const unsigned addrB = smem_u + ((brow * STRD + bcol) << 1);
    // V (trans) over the same smem region in pass 2
    const int vrow = ((lane >> 3) & 1) * 8 + (lane & 7);
    const int vcol = ((lane >> 4) & 1) * 8;
    const unsigned addrV = smem_u + ((vrow * STRD + vcol) << 1);

    // ---- Q prologue: stage fp32->fp16 (all 128 rows), load A-fragments ----
    #pragma unroll
    for (int i = tid; i < TQ * 16; i += NTH) {
        int r = i >> 4, c = (i & 15) * 4;
        float4 v = *(const float4*)(Qg + (size_t)r * Dc + c);
        __half2 p0 = __floats2half2_rn(v.x, v.y), p1 = __floats2half2_rn(v.z, v.w);
        uint2 u; u.x = *(unsigned*)&p0; u.y = *(unsigned*)&p1;
        *(uint2*)(smem_buf + r * STRD + c) = u;
    }
    __syncthreads();
    unsigned qa[2][4][4];
    #pragma unroll
    for (int mb = 0; mb < 2; ++mb) {
        unsigned addrA = smem_u +
            (((wq + 16 * mb + (lane & 15)) * STRD + (lane >> 4) * 8) << 1);
        #pragma unroll
        for (int ks = 0; ks < 4; ++ks)
            ldsm4(qa[mb][ks][0], qa[mb][ks][1], qa[mb][ks][2], qa[mb][ks][3],
                  addrA + ks * 32);
    }

    // ---------------- pass 1: scores -> exp fragments + Z ----------------
    float z[2][2] = {{0.0f, 0.0f}, {0.0f, 0.0f}};
    for (int kt = 0; kt < NKT; ++kt) {
        // FM fragment loads issued early (independent of smem)
        uint4 fm[2][4];
        #pragma unroll
        for (int mb = 0; mb < 2; ++mb) {
            const uint4* fp = fmb + ((size_t)kt * 8 + mb) * 128;
            fm[mb][0] = fp[0];  fm[mb][1] = fp[32];
            fm[mb][2] = fp[64]; fm[mb][3] = fp[96];
        }

        __syncthreads();
        #pragma unroll
        for (int i = tid; i < TK * 8; i += NTH) {      // K tile (uint4 copy)
            int r = i >> 3, c = (i & 7) * 8;
            *(uint4*)(Ks + r * STRD + c) =
                *(const uint4*)(Kh + (size_t)(kt * TK + r) * Dc + c);
        }
        __syncthreads();

        float sacc[2][8][4];
        #pragma unroll
        for (int mb = 0; mb < 2; ++mb)
            #pragma unroll
            for (int nt = 0; nt < 8; ++nt)
                sacc[mb][nt][0] = sacc[mb][nt][1] = sacc[mb][nt][2] = sacc[mb][nt][3] = 0.0f;

        #pragma unroll
        for (int ks = 0; ks < 4; ++ks) {
            unsigned bf[4][4];
            #pragma unroll
            for (int ntp = 0; ntp < 4; ++ntp)
                ldsm4(bf[ntp][0], bf[ntp][1], bf[ntp][2], bf[ntp][3],
                      addrB + (ntp * 16 * STRD + ks * 16) * 2);
            #pragma unroll
            for (int mb = 0; mb < 2; ++mb)
                #pragma unroll
                for (int ntp = 0; ntp < 4; ++ntp) {
                    mma_f16(sacc[mb][2 * ntp],     qa[mb][ks], &bf[ntp][0]);
                    mma_f16(sacc[mb][2 * ntp + 1], qa[mb][ks], &bf[ntp][2]);
                }
        }

        // exp with FM registers; store unnormalized fp16 exp fragments
        #pragma unroll
        for (int mb = 0; mb < 2; ++mb) {
            unsigned sl[8], sh[8];
            #pragma unroll
            for (int nt = 0; nt < 8; ++nt) {
                unsigned flo_u = ((const unsigned*)&fm[mb][nt >> 2])[nt & 3];
                unsigned fhi_u = ((const unsigned*)&fm[mb][2 + (nt >> 2)])[nt & 3];
                float2 flo = __half22float2(*(__half2*)&flo_u);
                float2 fhi = __half22float2(*(__half2*)&fhi_u);
                float p0 = __expf(fmaf(sacc[mb][nt][0], SCALE, flo.x));
                float p1 = __expf(fmaf(sacc[mb][nt][1], SCALE, flo.y));
                float p2 = __expf(fmaf(sacc[mb][nt][2], SCALE, fhi.x));
                float p3 = __expf(fmaf(sacc[mb][nt][3], SCALE, fhi.y));
                z[mb][0] += p0 + p1;
                z[mb][1] += p2 + p3;
                __half2 hlo = __floats2half2_rn(p0, p1);
                __half2 hhi = __floats2half2_rn(p2, p3);
                sl[nt] = *(unsigned*)&hlo;
                sh[nt] = *(unsigned*)&hhi;
            }
            uint4* sp = scr + ((size_t)kt * 8 + mb) * 128;
            sp[0]  = make_uint4(sl[0], sl[1], sl[2], sl[3]);
            sp[32] = make_uint4(sl[4], sl[5], sl[6], sl[7]);
            sp[64] = make_uint4(sh[0], sh[1], sh[2], sh[3]);
            sp[96] = make_uint4(sh[4], sh[5], sh[6], sh[7]);
        }
    }
    float iz[2][2];
    #pragma unroll
    for (int mb = 0; mb < 2; ++mb)
        #pragma unroll
        for (int hf = 0; hf < 2; ++hf) {
            float zz = z[mb][hf];
            zz += __shfl_xor_sync(0xffffffffu, zz, 1);
            zz += __shfl_xor_sync(0xffffffffu, zz, 2);
            iz[mb][hf] = 1.0f / zz;
        }

    // -------- pass 2 (REVERSED kt): normalize P + PV; scratch tail hits L2 --------
    float oacc[2][8][4];
    #pragma unroll
    for (int mb = 0; mb < 2; ++mb)
        #pragma unroll
        for (int nt = 0; nt < 8; ++nt)
            oacc[mb][nt][0] = oacc[mb][nt][1] = oacc[mb][nt][2] = oacc[mb][nt][3] = 0.0f;

    float2* Pp[2][2];
    #pragma unroll
    for (int mb = 0; mb < 2; ++mb) {
        Pp[mb][0] = (float2*)(Pg + (size_t)(wq + 16 * mb + g) * Sc) + tg;
        Pp[mb][1] = (float2*)(Pg + (size_t)(wq + 16 * mb + g + 8) * Sc) + tg;
    }

    for (int kt = NKT - 1; kt >= 0; --kt) {
        // scratch readback issued early; __ldcs = evict-first (read-once data)
        unsigned sl[2][8], sh[2][8];
        #pragma unroll
        for (int mb = 0; mb < 2; ++mb) {
            const uint4* sp = scr + ((size_t)kt * 8 + mb) * 128;
            uint4 a0 = __ldcs(sp);
            uint4 a1 = __ldcs(sp + 32);
            uint4 a2 = __ldcs(sp + 64);
            uint4 a3 = __ldcs(sp + 96);
            sl[mb][0] = a0.x; sl[mb][1] = a0.y; sl[mb][2] = a0.z; sl[mb][3] = a0.w;
            sl[mb][4] = a1.x; sl[mb][5] = a1.y; sl[mb][6] = a1.z; sl[mb][7] = a1.w;
            sh[mb][0] = a2.x; sh[mb][1] = a2.y; sh[mb][2] = a2.z; sh[mb][3] = a2.w;
            sh[mb][4] = a3.x; sh[mb][5] = a3.y; sh[mb][6] = a3.z; sh[mb][7] = a3.w;
        }

        __syncthreads();
        #pragma unroll
        for (int i = tid; i < TK * 8; i += NTH) {      // V tile (overlays Ks)
            int r = i >> 3, c = (i & 7) * 8;
            *(uint4*)(Ks + r * STRD + c) =
                *(const uint4*)(Vh + (size_t)(kt * TK + r) * Dc + c);
        }
        __syncthreads();

        // emit normalized fp32 P
        if (writep) {
            #pragma unroll
            for (int mb = 0; mb < 2; ++mb)
                #pragma unroll
                for (int nt = 0; nt < 8; ++nt) {
                    float2 plo = __half22float2(*(__half2*)&sl[mb][nt]);
                    float2 phi = __half22float2(*(__half2*)&sh[mb][nt]);
                    __stwt(Pp[mb][0] + kt * 32 + nt * 4,
                           make_float2(plo.x * iz[mb][0], plo.y * iz[mb][0]));
                    __stwt(Pp[mb][1] + kt * 32 + nt * 4,
                           make_float2(phi.x * iz[mb][1], phi.y * iz[mb][1]));
                }
        }

        // PV with unnormalized fp16 fragments (scale at the end)
        #pragma unroll
        for (int ks2 = 0; ks2 < 4; ++ks2) {
            #pragma unroll
            for (int ntp = 0; ntp < 4; ++ntp) {
                unsigned v0, v1, v2, v3;
                ldsm4t(v0, v1, v2, v3, addrV + (ks2 * 16 * STRD + ntp * 16) * 2);
                unsigned blo[2] = {v0, v1}, bhi[2] = {v2, v3};
                #pragma unroll
                for (int mb = 0; mb < 2; ++mb) {
                    unsigned a[4] = {sl[mb][2 * ks2], sh[mb][2 * ks2],
                                     sl[mb][2 * ks2 + 1], sh[mb][2 * ks2 + 1]};
                    mma_f16(oacc[mb][2 * ntp],     a, blo);
                    mma_f16(oacc[mb][2 * ntp + 1], a, bhi);
                }
            }
        }
    }

    // scale by 1/Z and write O tile
    #pragma unroll
    for (int mb = 0; mb < 2; ++mb) {
        float* o0 = Og + (size_t)(wq + 16 * mb + g) * Dc;
        float* o1 = Og + (size_t)(wq + 16 * mb + g + 8) * Dc;
        #pragma unroll
        for (int nt = 0; nt < 8; ++nt) {
            int col = nt * 8 + 2 * tg;
            *(float2*)(o0 + col) = make_float2(oacc[mb][nt][0] * iz[mb][0],
                                               oacc[mb][nt][1] * iz[mb][0]);
            *(float2*)(o1 + col) = make_float2(oacc[mb][nt][2] * iz[mb][1],
                                               oacc[mb][nt][3] * iz[mb][1]);
        }
    }
}

extern "C" void kernel_launch(void* const* d_in, const int* in_sizes, int n_in,
                              void* d_out, int out_size) {
    const float* Q    = (const float*)d_in[0];
    const float* K    = (const float*)d_in[1];
    const float* V    = (const float*)d_in[2];
    const float* freq = (const float*)d_in[3];
    const int*   mask = (const int*)d_in[4];

    const size_t out_elems = (size_t)Bc * Hc * Sc * Dc;   // 3,145,728
    float* Out  = (float*)d_out;
    float* Pout = (float*)d_out + out_elems;              // p_attn follows out
    int writep  = (out_size > (int)out_elems) ? 1 : 0;

    {
        int kv_blocks = (Bc * Hc * Sc * Dc) / (256 * 8);
        prep_kernel<<<FM_BLOCKS + kv_blocks, 256>>>(freq, mask, K, V);
    }
    {
        dim3 grid(Hc, Sc / TQ, Bc);
        attn_kernel<<<grid, NTH>>>(Q, Out, Pout, writep);
    }
}